// round 11
// baseline (speedup 1.0000x reference)
#include <cuda_runtime.h>
#include <cuda_bf16.h>

// out[i,j,:] = W[:,p] + W[:,66+t] + e*W[:,132] + W[:,133+s]
//
// Fused table (138 rows x 128 ch, channel-contiguous), as in R4:
//   T[r]     = W[:,r]  + W[:,131]     (r in 0..65)   covers (p, t=131)
//   T[66+dt] = W[:,32] + W[:,66+dt]   (dt in 0..65)  covers (p=32, t) [ri==rj]
//   T[132+k] = W[:,133+k] + (k<5 ? W[:,132] : 0)     entity-folded chain rows
// Hot loop: o = T[pt] + T[ch] -> 2 LDS.128 + 1 STG.128, branch-free, in-order.
//
// R8: PERSISTENT CTAs. grid=148 (1 CTA/SM), 1024 threads. Each CTA copies the
// 70.6KB table into SMEM ONCE, then loops over ~7 assigned rows. Table-copy
// traffic drops 1024 -> 148 copies; per-row prologue is 1 j per thread.

#define N_TBL_ROWS 138
#define CZ 128
#define NO_BINS 139
#define THREADS 1024
#define NWARPS (THREADS / 32)
#define GRID 148

__device__ float g_tbl[N_TBL_ROWS * CZ];

__global__ void build_tbl_kernel(const float* __restrict__ W) {
    int idx = blockIdx.x * blockDim.x + threadIdx.x;
    if (idx >= N_TBL_ROWS * CZ) return;
    int row = idx >> 7;        // 0..137
    int c   = idx & (CZ - 1);  // 0..127
    const float* Wc = W + c * NO_BINS;
    float v;
    if (row < 66) {
        v = Wc[row] + Wc[131];            // (p, t=131) fused
    } else if (row < 132) {
        v = Wc[32] + Wc[row];             // (p=32, t) fused (ri==rj case)
    } else {
        int k = row - 132;                // 0..5
        v = Wc[133 + k];
        if (k < 5) v += Wc[132];          // entity flag folded in
    }
    g_tbl[idx] = v;
}

__global__ __launch_bounds__(THREADS, 1) void relpos_kernel(
    const int* __restrict__ asym,
    const int* __restrict__ res,
    const int* __restrict__ ent,
    const int* __restrict__ tok,
    const int* __restrict__ sym,
    float* __restrict__ out,
    int N)
{
    extern __shared__ float smem[];
    float*    s_tbl = smem;                                   // 138*128 floats
    unsigned* s_idx = (unsigned*)(smem + N_TBL_ROWS * CZ);    // N packed indices

    const int tid  = threadIdx.x;
    const int warp = tid >> 5;
    const int lane = tid & 31;

    // --- Table -> SMEM ONCE per CTA (coalesced float4, conflict-free) ---
    {
        float4*       dst = (float4*)s_tbl;
        const float4* src = (const float4*)g_tbl;
        #pragma unroll
        for (int k = tid; k < (N_TBL_ROWS * CZ) / 4; k += THREADS) dst[k] = src[k];
    }

    // This thread's j-side features (one j per thread; reused across all rows)
    const int j  = tid;
    const int aj = __ldg(asym + j);
    const int rj = __ldg(res  + j);
    const int ej = __ldg(ent  + j);
    const int tj = __ldg(tok  + j);
    const int sj = __ldg(sym  + j);

    const float4* tbl4 = (const float4*)s_tbl;

    // --- Persistent row loop: rows b, b+148, ... ---
    for (int i = blockIdx.x; i < N; i += GRID) {
        const int ai = __ldg(asym + i);
        const int ri = __ldg(res  + i);
        const int ei = __ldg(ent  + i);
        const int ti = __ldg(tok  + i);
        const int si = __ldg(sym  + i);

        // per-j fused indices (pt, ch) packed into one u32
        {
            bool sc = (ai == aj);
            bool sr = (ri == rj);

            int p  = min(max(ri - rj + 32, 0), 64);   // 0..64
            int dt = min(max(ti - tj + 32, 0), 64);   // 0..64
            int pt = sc ? (sr ? (66 + dt) : p) : 65;

            int ds = min(max(si - sj + 2, 0), 4);
            int ch = (ei == ej) ? (132 + ds) : 137;

            s_idx[j] = (unsigned)pt | ((unsigned)ch << 8);
        }
        __syncthreads();

        // Hot loop: warp-per-pair, in-order, branch-free: 2 LDS.128 + STG.128
        float* orow = out + (size_t)i * N * CZ + lane * 4;

        #pragma unroll 4
        for (int jj = warp; jj < N; jj += NWARPS) {
            unsigned pk = s_idx[jj];
            int pt = pk & 0xFFu;
            int ch = pk >> 8;

            float4 a = tbl4[pt * 32 + lane];
            float4 c = tbl4[ch * 32 + lane];

            float4 o;
            o.x = a.x + c.x;
            o.y = a.y + c.y;
            o.z = a.z + c.z;
            o.w = a.w + c.w;

            __stcs((float4*)(orow + (size_t)jj * CZ), o);
        }
        __syncthreads();   // protect s_idx before next row's prologue
    }
}

extern "C" void kernel_launch(void* const* d_in, const int* in_sizes, int n_in,
                              void* d_out, int out_size) {
    const int*   asym = (const int*)d_in[0];
    const int*   res  = (const int*)d_in[1];
    const int*   ent  = (const int*)d_in[2];
    const int*   tok  = (const int*)d_in[3];
    const int*   sym  = (const int*)d_in[4];
    const float* W    = (const float*)d_in[5];
    float*       out  = (float*)d_out;

    const int N = in_sizes[0];  // 1024

    build_tbl_kernel<<<(N_TBL_ROWS * CZ + 255) / 256, 256>>>(W);

    const int smem_bytes = N_TBL_ROWS * CZ * (int)sizeof(float) + N * (int)sizeof(unsigned);
    cudaFuncSetAttribute(relpos_kernel, cudaFuncAttributeMaxDynamicSharedMemorySize, smem_bytes);
    relpos_kernel<<<GRID, THREADS, smem_bytes>>>(asym, res, ent, tok, sym, out, N);
}

// round 12
// speedup vs baseline: 1.0273x; 1.0273x over previous
#include <cuda_runtime.h>
#include <cuda_bf16.h>

// out[i,j,:] = W[:,p] + W[:,66+t] + e*W[:,132] + W[:,133+s]
//
// Fused table (138 rows x 128 ch, channel-contiguous), as in R4/R7:
//   T[r]     = W[:,r]  + W[:,131]     (r in 0..65)   covers (p, t=131)
//   T[66+dt] = W[:,32] + W[:,66+dt]   (dt in 0..65)  covers (p=32, t) [ri==rj]
//   T[132+k] = W[:,133+k] + (k<5 ? W[:,132] : 0)     entity-folded chain rows
// Hot loop: o = T[pt] + T[ch], branch-free, in-order, warp-per-pair.
//
// R9 = R7 + warp-uniform PREDICATED table loads:
//   pt==65 (~87.5%) -> first  LDS off, value = register a65
//   ch==137 (~75%)  -> second LDS off, value = register c137
// Fresh output registers every iteration (no cross-iteration carry chain),
// single predicated instructions (no BSSY/BSYNC), stores untouched.

#define N_TBL_ROWS 138
#define CZ 128
#define NO_BINS 139
#define THREADS 512
#define NWARPS (THREADS / 32)

__device__ float g_tbl[N_TBL_ROWS * CZ];

__global__ void build_tbl_kernel(const float* __restrict__ W) {
    int idx = blockIdx.x * blockDim.x + threadIdx.x;
    if (idx >= N_TBL_ROWS * CZ) return;
    int row = idx >> 7;        // 0..137
    int c   = idx & (CZ - 1);  // 0..127
    const float* Wc = W + c * NO_BINS;
    float v;
    if (row < 66) {
        v = Wc[row] + Wc[131];            // (p, t=131) fused
    } else if (row < 132) {
        v = Wc[32] + Wc[row];             // (p=32, t) fused (ri==rj case)
    } else {
        int k = row - 132;                // 0..5
        v = Wc[133 + k];
        if (k < 5) v += Wc[132];          // entity flag folded in
    }
    g_tbl[idx] = v;
}

__global__ __launch_bounds__(THREADS, 3) void relpos_kernel(
    const int* __restrict__ asym,
    const int* __restrict__ res,
    const int* __restrict__ ent,
    const int* __restrict__ tok,
    const int* __restrict__ sym,
    float* __restrict__ out,
    int N)
{
    extern __shared__ float smem[];
    float*    s_tbl = smem;                                   // 138*128 floats
    unsigned* s_idx = (unsigned*)(smem + N_TBL_ROWS * CZ);    // N packed indices

    const int tid = threadIdx.x;
    const int i   = blockIdx.x;

    // --- Prologue A: table -> SMEM (coalesced float4, conflict-free) ---
    {
        float4*       dst = (float4*)s_tbl;
        const float4* src = (const float4*)g_tbl;
        #pragma unroll
        for (int k = tid; k < (N_TBL_ROWS * CZ) / 4; k += THREADS) dst[k] = src[k];
    }

    // --- Prologue B: per-j fused indices (pt, ch) packed into one u32 ---
    const int ai = __ldg(asym + i);
    const int ri = __ldg(res  + i);
    const int ei = __ldg(ent  + i);
    const int ti = __ldg(tok  + i);
    const int si = __ldg(sym  + i);

    for (int j = tid; j < N; j += THREADS) {
        int aj = __ldg(asym + j);
        int rj = __ldg(res  + j);
        int ej = __ldg(ent  + j);
        int tj = __ldg(tok  + j);
        int sj = __ldg(sym  + j);

        bool sc = (ai == aj);
        bool sr = (ri == rj);

        int p  = min(max(ri - rj + 32, 0), 64);   // 0..64
        int dt = min(max(ti - tj + 32, 0), 64);   // 0..64
        int pt = sc ? (sr ? (66 + dt) : p) : 65;

        int ds = min(max(si - sj + 2, 0), 4);
        int ch = (ei == ej) ? (132 + ds) : 137;

        s_idx[j] = (unsigned)pt | ((unsigned)ch << 8);
    }
    __syncthreads();

    // --- Hot loop ---
    const int warp = tid >> 5;
    const int lane = tid & 31;
    const float4* tbl4 = (const float4*)s_tbl;

    // u32 shared address of this lane's 16B slice of table row 0
    unsigned tbl_base = (unsigned)__cvta_generic_to_shared(s_tbl) + (lane << 4);

    // register-resident defaults for the predicated-off cases
    const float4 a65  = tbl4[65  * 32 + lane];   // T[65]  (off-chain pt)
    const float4 c137 = tbl4[137 * 32 + lane];   // T[137] (off-entity ch)

    float* orow = out + (size_t)i * N * CZ + lane * 4;

    #pragma unroll 4
    for (int j = warp; j < N; j += NWARPS) {
        unsigned pk = s_idx[j];                  // LDS broadcast (warp-uniform)
        unsigned pt = pk & 0xFFu;
        unsigned ch = pk >> 8;
        unsigned addrA = tbl_base + (pt << 9);   // row stride = 512 B
        unsigned addrC = tbl_base + (ch << 9);

        // Fresh locals each iteration: init from defaults (renamable MOVs),
        // overwritten by a single predicated LDS.128 when the row is non-default.
        float ax = a65.x,  ay = a65.y,  az = a65.z,  aw = a65.w;
        float cx = c137.x, cy = c137.y, cz = c137.z, cw = c137.w;

        asm("{\n\t"
            ".reg .pred p;\n\t"
            "setp.ne.u32 p, %4, 65;\n\t"
            "@p ld.shared.v4.f32 {%0,%1,%2,%3}, [%5];\n\t"
            "}"
            : "+f"(ax), "+f"(ay), "+f"(az), "+f"(aw)
            : "r"(pt), "r"(addrA));

        asm("{\n\t"
            ".reg .pred p;\n\t"
            "setp.ne.u32 p, %4, 137;\n\t"
            "@p ld.shared.v4.f32 {%0,%1,%2,%3}, [%5];\n\t"
            "}"
            : "+f"(cx), "+f"(cy), "+f"(cz), "+f"(cw)
            : "r"(ch), "r"(addrC));

        float4 o;
        o.x = ax + cx;
        o.y = ay + cy;
        o.z = az + cz;
        o.w = aw + cw;

        __stcs((float4*)(orow + (size_t)j * CZ), o);
    }
}

extern "C" void kernel_launch(void* const* d_in, const int* in_sizes, int n_in,
                              void* d_out, int out_size) {
    const int*   asym = (const int*)d_in[0];
    const int*   res  = (const int*)d_in[1];
    const int*   ent  = (const int*)d_in[2];
    const int*   tok  = (const int*)d_in[3];
    const int*   sym  = (const int*)d_in[4];
    const float* W    = (const float*)d_in[5];
    float*       out  = (float*)d_out;

    const int N = in_sizes[0];  // 1024

    build_tbl_kernel<<<(N_TBL_ROWS * CZ + 255) / 256, 256>>>(W);

    const int smem_bytes = N_TBL_ROWS * CZ * (int)sizeof(float) + N * (int)sizeof(unsigned);
    cudaFuncSetAttribute(relpos_kernel, cudaFuncAttributeMaxDynamicSharedMemorySize, smem_bytes);
    relpos_kernel<<<N, THREADS, smem_bytes>>>(asym, res, ent, tok, sym, out, N);
}